// round 3
// baseline (speedup 1.0000x reference)
#include <cuda_runtime.h>
#include <cuda_bf16.h>

// GriddingDistance forward: trilinear scatter of two point clouds into two
// B x R x R x R occupancy-weight grids (concatenated: pred first, gt second).
//
// R3: single persistent kernel; processes the 32 (cloud,batch) 8MB grid
// regions in 8 phases of 4 regions (32MB, L2-resident). Each phase:
//   - all blocks zero the region group in-kernel (zeros live in L2, no DRAM)
//   - one-sided software barrier (per-phase counter, reset per launch)
//   - scatter that phase's points with L2-hit atomics
// Zeroing of phase p+1 is issued before waiting on phase p (overlap).

#ifndef GRID_B
#define GRID_B 16
#endif

#define NBLOCKS 592            // 4 per SM on 148 SMs; all co-resident (<= 8/SM cap)
#define TPB     256
#define NREG    (2 * GRID_B)   // 32 regions (pred batches then gt batches)
#define RPP     4              // regions per phase (4 * 8MB = 32MB << L2)
#define NPH     (NREG / RPP)   // 8 phases
#define PH_PRED (GRID_B / RPP) // 4 phases belong to pred cloud

__device__ unsigned g_cnt[NPH];   // phase arrival counters (memset to 0 each launch)

__device__ __forceinline__ void red_add_v2(float* p, float a, float b) {
    asm volatile("red.global.add.v2.f32 [%0], {%1, %2};"
                 :: "l"(p), "f"(a), "f"(b) : "memory");
}

__device__ __forceinline__ void scatter_point(
    float cx, float cy, float cz,
    float* __restrict__ dstBase,   // region base (out + r * R^3)
    int R, float Rf, float invR, bool evenR)
{
    float vx = (cx * invR + 0.5f) * Rf;
    float vy = (cy * invR + 0.5f) * Rf;
    float vz = (cz * invR + 0.5f) * Rf;

    float flx = floorf(vx), fly = floorf(vy), flz = floorf(vz);
    int ix = (int)flx, iy = (int)fly, iz = (int)flz;
    float fx = vx - flx, fy = vy - fly, fz = vz - flz;

    float wx0 = 1.0f - fx, wx1 = fx;
    float wy0 = 1.0f - fy, wy1 = fy;
    float wz0 = 1.0f - fz, wz1 = fz;

    long long sY = R;
    long long sX = (long long)R * R;

    if (ix >= 0 && iy >= 0 && iz >= 0 && ix + 1 < R && iy + 1 < R && iz + 1 < R) {
        long long i000 = ((long long)ix * R + iy) * R + iz;
        float* g = dstBase + i000;
        if (evenR && ((i000 & 1LL) == 0)) {
            red_add_v2(g,           wx0 * wy0 * wz0, wx0 * wy0 * wz1);
            red_add_v2(g + sY,      wx0 * wy1 * wz0, wx0 * wy1 * wz1);
            red_add_v2(g + sX,      wx1 * wy0 * wz0, wx1 * wy0 * wz1);
            red_add_v2(g + sX + sY, wx1 * wy1 * wz0, wx1 * wy1 * wz1);
        } else {
            atomicAdd(g,               wx0 * wy0 * wz0);
            atomicAdd(g + 1,           wx0 * wy0 * wz1);
            atomicAdd(g + sY,          wx0 * wy1 * wz0);
            atomicAdd(g + sY + 1,      wx0 * wy1 * wz1);
            atomicAdd(g + sX,          wx1 * wy0 * wz0);
            atomicAdd(g + sX + 1,      wx1 * wy0 * wz1);
            atomicAdd(g + sX + sY,     wx1 * wy1 * wz0);
            atomicAdd(g + sX + sY + 1, wx1 * wy1 * wz1);
        }
    } else {
        // Boundary path (reference: invalid corner contributes 0 -> skip)
        float wxa[2] = {wx0, wx1};
        float wya[2] = {wy0, wy1};
        float wza[2] = {wz0, wz1};
        #pragma unroll
        for (int dx = 0; dx < 2; dx++) {
            int x = ix + dx;
            if (x < 0 || x >= R) continue;
            #pragma unroll
            for (int dy = 0; dy < 2; dy++) {
                int y = iy + dy;
                if (y < 0 || y >= R) continue;
                #pragma unroll
                for (int dz = 0; dz < 2; dz++) {
                    int z = iz + dz;
                    if (z < 0 || z >= R) continue;
                    atomicAdd(dstBase + ((long long)x * R + y) * R + z,
                              wxa[dx] * wya[dy] * wza[dz]);
                }
            }
        }
    }
}

__global__ void __launch_bounds__(TPB)
gridding_phased_kernel(
    const float* __restrict__ pred,
    const float* __restrict__ gt,
    float* __restrict__ out,
    int npbPred, int npbGt,      // points per batch per cloud
    int R, float Rf, float invR,
    long long R3)                // cells per region
{
    const int tid = threadIdx.x;
    const unsigned gtid = blockIdx.x * TPB + tid;
    const bool evenR = ((R & 1) == 0);
    const long long phaseFloats = (long long)RPP * R3;

    // ---- zero a phase's region group (grid-strided float4 stores) ----
    auto zero_phase = [&](int p) {
        float4* base = (float4*)(out + (long long)p * phaseFloats);
        long long n4 = phaseFloats >> 2;
        float4 z = make_float4(0.f, 0.f, 0.f, 0.f);
        for (long long q = gtid; q < n4; q += (long long)NBLOCKS * TPB)
            base[q] = z;
        long long rem = phaseFloats & 3LL;
        if (rem && blockIdx.x == 0 && tid < rem)
            out[(long long)p * phaseFloats + (n4 << 2) + tid] = 0.f;
        __syncthreads();
        if (tid == 0) {
            __threadfence();
            atomicAdd(&g_cnt[p], 1u);
        }
    };

    auto wait_phase = [&](int p) {
        if (tid == 0) {
            unsigned v;
            while (true) {
                asm volatile("ld.acquire.gpu.global.u32 %0, [%1];"
                             : "=r"(v) : "l"(&g_cnt[p]) : "memory");
                if (v >= (unsigned)NBLOCKS) break;
                __nanosleep(128);
            }
        }
        __syncthreads();
    };

    zero_phase(0);

    for (int p = 0; p < NPH; p++) {
        if (p + 1 < NPH) zero_phase(p + 1);
        wait_phase(p);

        // ---- scatter this phase's points ----
        const bool isPred = (p < PH_PRED);
        const float* __restrict__ src = isPred ? pred : gt;
        const int npb = isPred ? npbPred : npbGt;
        const int cloudPhase = isPred ? p : (p - PH_PRED);
        const long long ptsPerPhase = (long long)RPP * npb;

        for (long long j = gtid; j < ptsPerPhase; j += (long long)NBLOCKS * TPB) {
            int rloc = (int)(j / npb);                 // region within phase
            long long i = j - (long long)rloc * npb;   // point within batch
            int rGlobal = p * RPP + rloc;              // output region index
            long long srcPt = ((long long)(cloudPhase * RPP + rloc) * npb + i) * 3;
            float cx = src[srcPt + 0];
            float cy = src[srcPt + 1];
            float cz = src[srcPt + 2];
            scatter_point(cx, cy, cz, out + (long long)rGlobal * R3,
                          R, Rf, invR, evenR);
        }
    }
}

static inline int icbrt(long long v) {
    int r = (int)llroundf(cbrtf((float)v));
    while ((long long)(r + 1) * (r + 1) * (r + 1) <= v) r++;
    while ((long long)r * r * r > v) r--;
    return r;
}

extern "C" void kernel_launch(void* const* d_in, const int* in_sizes, int n_in,
                              void* d_out, int out_size)
{
    const float* pred = (const float*)d_in[0];
    const float* gt   = (const float*)d_in[1];
    float* out = (float*)d_out;

    int nPred = in_sizes[0] / 3;
    int nGt   = in_sizes[1] / 3;
    int B = GRID_B;
    long long cellsPerCloud = (long long)out_size / 2;   // B * R^3
    long long R3 = cellsPerCloud / B;                    // R^3
    int R = icbrt(R3);
    float Rf = (float)R;
    float invR = 1.0f / Rf;

    int npbPred = nPred / B;
    int npbGt   = nGt / B;

    // reset phase counters (tiny, graph-capturable)
    void* cntAddr = nullptr;
    cudaGetSymbolAddress(&cntAddr, g_cnt);
    cudaMemsetAsync(cntAddr, 0, sizeof(unsigned) * NPH, 0);

    gridding_phased_kernel<<<NBLOCKS, TPB>>>(
        pred, gt, out, npbPred, npbGt, R, Rf, invR, R3);
}

// round 4
// speedup vs baseline: 1.1180x; 1.1180x over previous
#include <cuda_runtime.h>
#include <cuda_bf16.h>

// GriddingDistance forward: trilinear scatter of two point clouds into two
// B x R x R x R fp32 grids (concatenated in d_out: pred first, gt second).
//
// R4: overlap the 256MB zero-fill with the atomic scatter using a forked
// capture stream. Output split into 4 chunks (8 batches / 64MB each);
// chunk k's scatter waits only on chunk k's memset. The scatter kernel is
// the proven R2 body (vector red.global.add.v2 for even rows), 2 pts/thread
// via aligned float2 loads.

#ifndef GRID_B
#define GRID_B 16
#endif

#define NCHUNK 4                       // 2 per cloud, 8 batches (64MB) each
#define BPC    (2 * GRID_B / NCHUNK)   // batches per chunk = 8

__device__ __forceinline__ void red_add_v2(float* p, float a, float b) {
    asm volatile("red.global.add.v2.f32 [%0], {%1, %2};"
                 :: "l"(p), "f"(a), "f"(b) : "memory");
}

__device__ __forceinline__ void scatter_point(
    float cx, float cy, float cz,
    float* __restrict__ dstBase,   // batch-region base
    int R, float Rf, float invR, bool evenR)
{
    float vx = (cx * invR + 0.5f) * Rf;
    float vy = (cy * invR + 0.5f) * Rf;
    float vz = (cz * invR + 0.5f) * Rf;

    float flx = floorf(vx), fly = floorf(vy), flz = floorf(vz);
    int ix = (int)flx, iy = (int)fly, iz = (int)flz;
    float fx = vx - flx, fy = vy - fly, fz = vz - flz;

    float wx0 = 1.0f - fx, wx1 = fx;
    float wy0 = 1.0f - fy, wy1 = fy;
    float wz0 = 1.0f - fz, wz1 = fz;

    long long sY = R;
    long long sX = (long long)R * R;

    if (ix >= 0 && iy >= 0 && iz >= 0 && ix + 1 < R && iy + 1 < R && iz + 1 < R) {
        long long i000 = ((long long)ix * R + iy) * R + iz;
        float* g = dstBase + i000;
        if (evenR && ((i000 & 1LL) == 0)) {
            red_add_v2(g,           wx0 * wy0 * wz0, wx0 * wy0 * wz1);
            red_add_v2(g + sY,      wx0 * wy1 * wz0, wx0 * wy1 * wz1);
            red_add_v2(g + sX,      wx1 * wy0 * wz0, wx1 * wy0 * wz1);
            red_add_v2(g + sX + sY, wx1 * wy1 * wz0, wx1 * wy1 * wz1);
        } else {
            atomicAdd(g,               wx0 * wy0 * wz0);
            atomicAdd(g + 1,           wx0 * wy0 * wz1);
            atomicAdd(g + sY,          wx0 * wy1 * wz0);
            atomicAdd(g + sY + 1,      wx0 * wy1 * wz1);
            atomicAdd(g + sX,          wx1 * wy0 * wz0);
            atomicAdd(g + sX + 1,      wx1 * wy0 * wz1);
            atomicAdd(g + sX + sY,     wx1 * wy1 * wz0);
            atomicAdd(g + sX + sY + 1, wx1 * wy1 * wz1);
        }
    } else {
        // Boundary path (reference: invalid corner contributes 0 -> skip)
        float wxa[2] = {wx0, wx1};
        float wya[2] = {wy0, wy1};
        float wza[2] = {wz0, wz1};
        #pragma unroll
        for (int dx = 0; dx < 2; dx++) {
            int x = ix + dx;
            if (x < 0 || x >= R) continue;
            #pragma unroll
            for (int dy = 0; dy < 2; dy++) {
                int y = iy + dy;
                if (y < 0 || y >= R) continue;
                #pragma unroll
                for (int dz = 0; dz < 2; dz++) {
                    int z = iz + dz;
                    if (z < 0 || z >= R) continue;
                    atomicAdd(dstBase + ((long long)x * R + y) * R + z,
                              wxa[dx] * wya[dy] * wza[dz]);
                }
            }
        }
    }
}

// One chunk = `nBatches` consecutive batches of one cloud. 2 points/thread.
__global__ void __launch_bounds__(256)
gridding_scatter2_kernel(
    const float* __restrict__ cloud,   // chunk's first point (batch-aligned)
    float* __restrict__ dst,           // chunk's first batch-region base
    int nPts,                          // points in chunk (nBatches * npb)
    int npb,                           // points per batch
    int R, float Rf, float invR,
    long long R3)
{
    int t = blockIdx.x * blockDim.x + threadIdx.x;
    int p0 = t * 2;
    if (p0 >= nPts) return;
    bool evenR = ((R & 1) == 0);

    if (p0 + 2 <= nPts) {
        // 6 contiguous floats = 2 points, 3x LDG.64 (8B aligned: t*24 bytes)
        const float2* c2 = (const float2*)cloud;
        float2 a = c2[3 * t + 0];
        float2 b = c2[3 * t + 1];
        float2 c = c2[3 * t + 2];
        {
            long long base = (long long)(p0 / npb) * R3;
            scatter_point(a.x, a.y, b.x, dst + base, R, Rf, invR, evenR);
        }
        {
            long long base = (long long)((p0 + 1) / npb) * R3;
            scatter_point(b.y, c.x, c.y, dst + base, R, Rf, invR, evenR);
        }
    } else {
        int p = p0;
        long long base = (long long)(p / npb) * R3;
        scatter_point(cloud[3 * p + 0], cloud[3 * p + 1], cloud[3 * p + 2],
                      dst + base, R, Rf, invR, evenR);
    }
}

static inline int icbrt(long long v) {
    int r = (int)llroundf(cbrtf((float)v));
    while ((long long)(r + 1) * (r + 1) * (r + 1) <= v) r++;
    while ((long long)r * r * r > v) r--;
    return r;
}

// Side stream + events, created once on the first (uncaptured) correctness
// call; reused verbatim inside graph capture thereafter. No device memory.
struct OverlapCtx {
    cudaStream_t s1;
    cudaEvent_t  evFork;
    cudaEvent_t  evChunk[NCHUNK];
    OverlapCtx() {
        cudaStreamCreateWithFlags(&s1, cudaStreamNonBlocking);
        cudaEventCreateWithFlags(&evFork, cudaEventDisableTiming);
        for (int i = 0; i < NCHUNK; i++)
            cudaEventCreateWithFlags(&evChunk[i], cudaEventDisableTiming);
    }
};

extern "C" void kernel_launch(void* const* d_in, const int* in_sizes, int n_in,
                              void* d_out, int out_size)
{
    static OverlapCtx ctx;   // initialized on first (non-captured) call

    const float* pred = (const float*)d_in[0];
    const float* gt   = (const float*)d_in[1];
    float* out = (float*)d_out;

    int nPred = in_sizes[0] / 3;
    int nGt   = in_sizes[1] / 3;
    int B = GRID_B;
    long long cellsPerCloud = (long long)out_size / 2;   // B * R^3
    long long R3 = cellsPerCloud / B;                    // R^3
    int R = icbrt(R3);
    float Rf = (float)R;
    float invR = 1.0f / Rf;

    int npbPred = nPred / B;
    int npbGt   = nGt / B;

    long long chunkFloats = (long long)BPC * R3;   // cells per chunk

    // Fork: side stream joins the capture, then runs all memsets in order.
    cudaEventRecord(ctx.evFork, 0);
    cudaStreamWaitEvent(ctx.s1, ctx.evFork, 0);
    for (int k = 0; k < NCHUNK; k++) {
        cudaMemsetAsync(out + (long long)k * chunkFloats, 0,
                        (size_t)chunkFloats * sizeof(float), ctx.s1);
        cudaEventRecord(ctx.evChunk[k], ctx.s1);
    }

    // Main stream: scatter chunk k as soon as its memset lands.
    const int threads = 256;
    const int chunksPerCloud = NCHUNK / 2;
    for (int k = 0; k < NCHUNK; k++) {
        cudaStreamWaitEvent(0, ctx.evChunk[k], 0);

        bool isPred = (k < chunksPerCloud);
        const float* srcCloud = isPred ? pred : gt;
        int npb = isPred ? npbPred : npbGt;
        int ck = isPred ? k : (k - chunksPerCloud);   // chunk index within cloud
        int nPts = BPC * npb;

        const float* src = srcCloud + (long long)ck * BPC * npb * 3;
        float* dst = out + (long long)k * chunkFloats;

        int nThr = (nPts + 1) / 2;
        int blocks = (nThr + threads - 1) / threads;
        gridding_scatter2_kernel<<<blocks, threads>>>(
            src, dst, nPts, npb, R, Rf, invR, R3);
    }
    // Final scatter waits on evChunk[NCHUNK-1] -> side stream is rejoined.
}

// round 6
// speedup vs baseline: 1.2014x; 1.0746x over previous
#include <cuda_runtime.h>
#include <cuda_bf16.h>

// GriddingDistance forward: trilinear scatter of two point clouds into two
// B x R x R x R fp32 grids (concatenated in d_out: pred first, gt second).
//
// R6: R4's rule-clean overlap skeleton (ONE side stream for memsets, scatter
// chunk k gated on its own memset) + v4-window vector reductions:
// for R % 4 == 0, each xy-corner's z-pair maps into the 16B-aligned window
// (i000 & ~3) within the same row -> one red.global.add.v4.f32 with 0.0f
// padding (75% of points need just 4 REDG lanes total; 25% need 8).

#ifndef GRID_B
#define GRID_B 16
#endif

#define NCHUNK 4                       // 2 per cloud, 8 batches (64MB) each
#define BPC    (2 * GRID_B / NCHUNK)   // batches per chunk = 8

__device__ __forceinline__ void red_add_v4(float* p, float a, float b, float c, float d) {
    asm volatile("red.global.add.v4.f32 [%0], {%1, %2, %3, %4};"
                 :: "l"(p), "f"(a), "f"(b), "f"(c), "f"(d) : "memory");
}
__device__ __forceinline__ void red_add_v2(float* p, float a, float b) {
    asm volatile("red.global.add.v2.f32 [%0], {%1, %2};"
                 :: "l"(p), "f"(a), "f"(b) : "memory");
}

// One xy-corner: add (w0, w1) at cells [idx, idx+1] of row, via one v4 in the
// aligned window when the pair fits (pos<3), else v4 tail + scalar.
__device__ __forceinline__ void corner_pair(float* rowBase, long long idx,
                                            int pos, float w0, float w1)
{
    float* w = rowBase + (idx & ~3LL);
    if (pos == 0)      red_add_v4(w, w0, w1, 0.f, 0.f);
    else if (pos == 1) red_add_v4(w, 0.f, w0, w1, 0.f);
    else if (pos == 2) red_add_v4(w, 0.f, 0.f, w0, w1);
    else {             // pos == 3: pair straddles windows
        red_add_v4(w, 0.f, 0.f, 0.f, w0);
        atomicAdd(rowBase + idx + 1, w1);
    }
}

__device__ __forceinline__ void scatter_point(
    float cx, float cy, float cz,
    float* __restrict__ dstBase,   // batch-region base
    int R, float Rf, float invR, bool rMod4)
{
    float vx = (cx * invR + 0.5f) * Rf;
    float vy = (cy * invR + 0.5f) * Rf;
    float vz = (cz * invR + 0.5f) * Rf;

    float flx = floorf(vx), fly = floorf(vy), flz = floorf(vz);
    int ix = (int)flx, iy = (int)fly, iz = (int)flz;
    float fx = vx - flx, fy = vy - fly, fz = vz - flz;

    float wx0 = 1.0f - fx, wx1 = fx;
    float wy0 = 1.0f - fy, wy1 = fy;
    float wz0 = 1.0f - fz, wz1 = fz;

    long long sY = R;
    long long sX = (long long)R * R;

    if (ix >= 0 && iy >= 0 && iz >= 0 && ix + 1 < R && iy + 1 < R && iz + 1 < R) {
        long long i000 = ((long long)ix * R + iy) * R + iz;
        if (rMod4) {
            // R % 4 == 0: i000 & 3 == iz & 3, aligned window stays in-row.
            int pos = (int)(i000 & 3LL);
            corner_pair(dstBase, i000,           pos, wx0 * wy0 * wz0, wx0 * wy0 * wz1);
            corner_pair(dstBase, i000 + sY,      pos, wx0 * wy1 * wz0, wx0 * wy1 * wz1);
            corner_pair(dstBase, i000 + sX,      pos, wx1 * wy0 * wz0, wx1 * wy0 * wz1);
            corner_pair(dstBase, i000 + sX + sY, pos, wx1 * wy1 * wz0, wx1 * wy1 * wz1);
        } else if ((i000 & 1LL) == 0) {
            float* g = dstBase + i000;
            red_add_v2(g,           wx0 * wy0 * wz0, wx0 * wy0 * wz1);
            red_add_v2(g + sY,      wx0 * wy1 * wz0, wx0 * wy1 * wz1);
            red_add_v2(g + sX,      wx1 * wy0 * wz0, wx1 * wy0 * wz1);
            red_add_v2(g + sX + sY, wx1 * wy1 * wz0, wx1 * wy1 * wz1);
        } else {
            float* g = dstBase + i000;
            atomicAdd(g,               wx0 * wy0 * wz0);
            atomicAdd(g + 1,           wx0 * wy0 * wz1);
            atomicAdd(g + sY,          wx0 * wy1 * wz0);
            atomicAdd(g + sY + 1,      wx0 * wy1 * wz1);
            atomicAdd(g + sX,          wx1 * wy0 * wz0);
            atomicAdd(g + sX + 1,      wx1 * wy0 * wz1);
            atomicAdd(g + sX + sY,     wx1 * wy1 * wz0);
            atomicAdd(g + sX + sY + 1, wx1 * wy1 * wz1);
        }
    } else {
        // Boundary path (reference: invalid corner contributes 0 -> skip)
        float wxa[2] = {wx0, wx1};
        float wya[2] = {wy0, wy1};
        float wza[2] = {wz0, wz1};
        #pragma unroll
        for (int dx = 0; dx < 2; dx++) {
            int x = ix + dx;
            if (x < 0 || x >= R) continue;
            #pragma unroll
            for (int dy = 0; dy < 2; dy++) {
                int y = iy + dy;
                if (y < 0 || y >= R) continue;
                #pragma unroll
                for (int dz = 0; dz < 2; dz++) {
                    int z = iz + dz;
                    if (z < 0 || z >= R) continue;
                    atomicAdd(dstBase + ((long long)x * R + y) * R + z,
                              wxa[dx] * wya[dy] * wza[dz]);
                }
            }
        }
    }
}

// One chunk = BPC consecutive batches of one cloud. 2 points/thread.
__global__ void __launch_bounds__(256)
gridding_scatter2_kernel(
    const float* __restrict__ cloud,   // chunk's first point (batch-aligned)
    float* __restrict__ dst,           // chunk's first batch-region base
    int nPts,                          // points in chunk (BPC * npb)
    int npb,                           // points per batch
    int R, float Rf, float invR,
    long long R3)
{
    int t = blockIdx.x * blockDim.x + threadIdx.x;
    int p0 = t * 2;
    if (p0 >= nPts) return;
    bool rMod4 = ((R & 3) == 0);

    if (p0 + 2 <= nPts) {
        const float2* c2 = (const float2*)cloud;   // 8B-aligned: t*24 bytes
        float2 a = c2[3 * t + 0];
        float2 b = c2[3 * t + 1];
        float2 c = c2[3 * t + 2];
        {
            long long base = (long long)(p0 / npb) * R3;
            scatter_point(a.x, a.y, b.x, dst + base, R, Rf, invR, rMod4);
        }
        {
            long long base = (long long)((p0 + 1) / npb) * R3;
            scatter_point(b.y, c.x, c.y, dst + base, R, Rf, invR, rMod4);
        }
    } else {
        int p = p0;
        long long base = (long long)(p / npb) * R3;
        scatter_point(cloud[3 * p + 0], cloud[3 * p + 1], cloud[3 * p + 2],
                      dst + base, R, Rf, invR, rMod4);
    }
}

static inline int icbrt(long long v) {
    int r = (int)llroundf(cbrtf((float)v));
    while ((long long)(r + 1) * (r + 1) * (r + 1) <= v) r++;
    while ((long long)r * r * r > v) r--;
    return r;
}

// ONE side stream + events (R4-proven rule-clean), created on the first
// (uncaptured) correctness call; reused verbatim under graph capture.
struct OverlapCtx {
    cudaStream_t s1;
    cudaEvent_t  evFork;
    cudaEvent_t  evChunk[NCHUNK];
    OverlapCtx() {
        cudaStreamCreateWithFlags(&s1, cudaStreamNonBlocking);
        cudaEventCreateWithFlags(&evFork, cudaEventDisableTiming);
        for (int i = 0; i < NCHUNK; i++)
            cudaEventCreateWithFlags(&evChunk[i], cudaEventDisableTiming);
    }
};

extern "C" void kernel_launch(void* const* d_in, const int* in_sizes, int n_in,
                              void* d_out, int out_size)
{
    static OverlapCtx ctx;

    const float* pred = (const float*)d_in[0];
    const float* gt   = (const float*)d_in[1];
    float* out = (float*)d_out;

    int nPred = in_sizes[0] / 3;
    int nGt   = in_sizes[1] / 3;
    int B = GRID_B;
    long long cellsPerCloud = (long long)out_size / 2;   // B * R^3
    long long R3 = cellsPerCloud / B;                    // R^3
    int R = icbrt(R3);
    float Rf = (float)R;
    float invR = 1.0f / Rf;

    int npbPred = nPred / B;
    int npbGt   = nGt / B;

    long long chunkFloats = (long long)BPC * R3;   // cells per chunk

    // Fork: side stream joins the capture, runs all memsets in order.
    cudaEventRecord(ctx.evFork, 0);
    cudaStreamWaitEvent(ctx.s1, ctx.evFork, 0);
    for (int k = 0; k < NCHUNK; k++) {
        cudaMemsetAsync(out + (long long)k * chunkFloats, 0,
                        (size_t)chunkFloats * sizeof(float), ctx.s1);
        cudaEventRecord(ctx.evChunk[k], ctx.s1);
    }

    // Main stream: scatter chunk k as soon as its memset lands.
    const int threads = 256;
    const int chunksPerCloud = NCHUNK / 2;
    for (int k = 0; k < NCHUNK; k++) {
        cudaStreamWaitEvent(0, ctx.evChunk[k], 0);

        bool isPred = (k < chunksPerCloud);
        const float* srcCloud = isPred ? pred : gt;
        int npb = isPred ? npbPred : npbGt;
        int ck = isPred ? k : (k - chunksPerCloud);
        int nPts = BPC * npb;

        const float* src = srcCloud + (long long)ck * BPC * npb * 3;
        float* dst = out + (long long)k * chunkFloats;

        int nThr = (nPts + 1) / 2;
        int blocks = (nThr + threads - 1) / threads;
        gridding_scatter2_kernel<<<blocks, threads>>>(
            src, dst, nPts, npb, R, Rf, invR, R3);
    }
    // Final scatter waits on evChunk[NCHUNK-1] -> side stream rejoined.
}

// round 7
// speedup vs baseline: 1.9392x; 1.6141x over previous
#include <cuda_runtime.h>
#include <cuda_bf16.h>

// GriddingDistance forward: trilinear scatter of two point clouds into two
// B x R x R x R fp32 grids (concatenated in d_out: pred first, gt second).
//
// R7: 8 chunks of 32MB (4 batches each). ONE side stream zeroes chunk k;
// scatter k (main stream) waits on its memset. Memset k additionally waits
// on scatter k-2, so at most ~2 zeroed chunks (64MB < L2) are in flight:
// zeros stay L2-resident until their scatter consumes them -> atomics hit
// L2, zero-fill never round-trips DRAM. Scatter body = R6 v4-window REDG.

#ifndef GRID_B
#define GRID_B 16
#endif

#define NCHUNK 8                       // 4 per cloud, 4 batches (32MB) each
#define BPC    (2 * GRID_B / NCHUNK)   // batches per chunk = 4
#define AHEAD  2                       // memset k waits scatter[k-AHEAD]

__device__ __forceinline__ void red_add_v4(float* p, float a, float b, float c, float d) {
    asm volatile("red.global.add.v4.f32 [%0], {%1, %2, %3, %4};"
                 :: "l"(p), "f"(a), "f"(b), "f"(c), "f"(d) : "memory");
}
__device__ __forceinline__ void red_add_v2(float* p, float a, float b) {
    asm volatile("red.global.add.v2.f32 [%0], {%1, %2};"
                 :: "l"(p), "f"(a), "f"(b) : "memory");
}

// One xy-corner: add (w0, w1) at cells [idx, idx+1] via one v4 in the 16B
// window (pos<3), else v4 tail + scalar.
__device__ __forceinline__ void corner_pair(float* rowBase, long long idx,
                                            int pos, float w0, float w1)
{
    float* w = rowBase + (idx & ~3LL);
    if (pos == 0)      red_add_v4(w, w0, w1, 0.f, 0.f);
    else if (pos == 1) red_add_v4(w, 0.f, w0, w1, 0.f);
    else if (pos == 2) red_add_v4(w, 0.f, 0.f, w0, w1);
    else {
        red_add_v4(w, 0.f, 0.f, 0.f, w0);
        atomicAdd(rowBase + idx + 1, w1);
    }
}

__device__ __forceinline__ void scatter_point(
    float cx, float cy, float cz,
    float* __restrict__ dstBase,   // batch-region base
    int R, float Rf, float invR, bool rMod4)
{
    float vx = (cx * invR + 0.5f) * Rf;
    float vy = (cy * invR + 0.5f) * Rf;
    float vz = (cz * invR + 0.5f) * Rf;

    float flx = floorf(vx), fly = floorf(vy), flz = floorf(vz);
    int ix = (int)flx, iy = (int)fly, iz = (int)flz;
    float fx = vx - flx, fy = vy - fly, fz = vz - flz;

    float wx0 = 1.0f - fx, wx1 = fx;
    float wy0 = 1.0f - fy, wy1 = fy;
    float wz0 = 1.0f - fz, wz1 = fz;

    long long sY = R;
    long long sX = (long long)R * R;

    if (ix >= 0 && iy >= 0 && iz >= 0 && ix + 1 < R && iy + 1 < R && iz + 1 < R) {
        long long i000 = ((long long)ix * R + iy) * R + iz;
        if (rMod4) {
            int pos = (int)(i000 & 3LL);
            corner_pair(dstBase, i000,           pos, wx0 * wy0 * wz0, wx0 * wy0 * wz1);
            corner_pair(dstBase, i000 + sY,      pos, wx0 * wy1 * wz0, wx0 * wy1 * wz1);
            corner_pair(dstBase, i000 + sX,      pos, wx1 * wy0 * wz0, wx1 * wy0 * wz1);
            corner_pair(dstBase, i000 + sX + sY, pos, wx1 * wy1 * wz0, wx1 * wy1 * wz1);
        } else if ((i000 & 1LL) == 0) {
            float* g = dstBase + i000;
            red_add_v2(g,           wx0 * wy0 * wz0, wx0 * wy0 * wz1);
            red_add_v2(g + sY,      wx0 * wy1 * wz0, wx0 * wy1 * wz1);
            red_add_v2(g + sX,      wx1 * wy0 * wz0, wx1 * wy0 * wz1);
            red_add_v2(g + sX + sY, wx1 * wy1 * wz0, wx1 * wy1 * wz1);
        } else {
            float* g = dstBase + i000;
            atomicAdd(g,               wx0 * wy0 * wz0);
            atomicAdd(g + 1,           wx0 * wy0 * wz1);
            atomicAdd(g + sY,          wx0 * wy1 * wz0);
            atomicAdd(g + sY + 1,      wx0 * wy1 * wz1);
            atomicAdd(g + sX,          wx1 * wy0 * wz0);
            atomicAdd(g + sX + 1,      wx1 * wy0 * wz1);
            atomicAdd(g + sX + sY,     wx1 * wy1 * wz0);
            atomicAdd(g + sX + sY + 1, wx1 * wy1 * wz1);
        }
    } else {
        // Boundary path (reference: invalid corner contributes 0 -> skip)
        float wxa[2] = {wx0, wx1};
        float wya[2] = {wy0, wy1};
        float wza[2] = {wz0, wz1};
        #pragma unroll
        for (int dx = 0; dx < 2; dx++) {
            int x = ix + dx;
            if (x < 0 || x >= R) continue;
            #pragma unroll
            for (int dy = 0; dy < 2; dy++) {
                int y = iy + dy;
                if (y < 0 || y >= R) continue;
                #pragma unroll
                for (int dz = 0; dz < 2; dz++) {
                    int z = iz + dz;
                    if (z < 0 || z >= R) continue;
                    atomicAdd(dstBase + ((long long)x * R + y) * R + z,
                              wxa[dx] * wya[dy] * wza[dz]);
                }
            }
        }
    }
}

// One chunk = BPC consecutive batches of one cloud. 2 points/thread.
__global__ void __launch_bounds__(256)
gridding_scatter2_kernel(
    const float* __restrict__ cloud,
    float* __restrict__ dst,
    int nPts, int npb,
    int R, float Rf, float invR,
    long long R3)
{
    int t = blockIdx.x * blockDim.x + threadIdx.x;
    int p0 = t * 2;
    if (p0 >= nPts) return;
    bool rMod4 = ((R & 3) == 0);

    if (p0 + 2 <= nPts) {
        const float2* c2 = (const float2*)cloud;
        float2 a = c2[3 * t + 0];
        float2 b = c2[3 * t + 1];
        float2 c = c2[3 * t + 2];
        {
            long long base = (long long)(p0 / npb) * R3;
            scatter_point(a.x, a.y, b.x, dst + base, R, Rf, invR, rMod4);
        }
        {
            long long base = (long long)((p0 + 1) / npb) * R3;
            scatter_point(b.y, c.x, c.y, dst + base, R, Rf, invR, rMod4);
        }
    } else {
        int p = p0;
        long long base = (long long)(p / npb) * R3;
        scatter_point(cloud[3 * p + 0], cloud[3 * p + 1], cloud[3 * p + 2],
                      dst + base, R, Rf, invR, rMod4);
    }
}

static inline int icbrt(long long v) {
    int r = (int)llroundf(cbrtf((float)v));
    while ((long long)(r + 1) * (r + 1) * (r + 1) <= v) r++;
    while ((long long)r * r * r > v) r--;
    return r;
}

// ONE side stream + events (rule-clean R4 pattern), created on the first
// (uncaptured) correctness call; reused verbatim under graph capture.
struct OverlapCtx {
    cudaStream_t s1;
    cudaEvent_t  evFork;
    cudaEvent_t  evZero[NCHUNK];   // memset k done
    cudaEvent_t  evScat[NCHUNK];   // scatter k done
    OverlapCtx() {
        cudaStreamCreateWithFlags(&s1, cudaStreamNonBlocking);
        cudaEventCreateWithFlags(&evFork, cudaEventDisableTiming);
        for (int i = 0; i < NCHUNK; i++) {
            cudaEventCreateWithFlags(&evZero[i], cudaEventDisableTiming);
            cudaEventCreateWithFlags(&evScat[i], cudaEventDisableTiming);
        }
    }
};

extern "C" void kernel_launch(void* const* d_in, const int* in_sizes, int n_in,
                              void* d_out, int out_size)
{
    static OverlapCtx ctx;

    const float* pred = (const float*)d_in[0];
    const float* gt   = (const float*)d_in[1];
    float* out = (float*)d_out;

    int nPred = in_sizes[0] / 3;
    int nGt   = in_sizes[1] / 3;
    int B = GRID_B;
    long long cellsPerCloud = (long long)out_size / 2;   // B * R^3
    long long R3 = cellsPerCloud / B;                    // R^3
    int R = icbrt(R3);
    float Rf = (float)R;
    float invR = 1.0f / Rf;

    int npbPred = nPred / B;
    int npbGt   = nGt / B;

    long long chunkFloats = (long long)BPC * R3;
    const int chunksPerCloud = NCHUNK / 2;
    const int threads = 256;

    // Fork the side stream off the capture origin.
    cudaEventRecord(ctx.evFork, 0);
    cudaStreamWaitEvent(ctx.s1, ctx.evFork, 0);

    // Interleave: side stream zeroes chunk k (throttled to stay <= AHEAD
    // chunks ahead of the scatters); main stream scatters chunk k after its
    // memset. Record order keeps each event recorded before it is waited on.
    for (int k = 0; k < NCHUNK; k++) {
        // --- side stream: memset k ---
        if (k >= AHEAD)
            cudaStreamWaitEvent(ctx.s1, ctx.evScat[k - AHEAD], 0);
        cudaMemsetAsync(out + (long long)k * chunkFloats, 0,
                        (size_t)chunkFloats * sizeof(float), ctx.s1);
        cudaEventRecord(ctx.evZero[k], ctx.s1);

        // --- main stream: scatter k ---
        cudaStreamWaitEvent(0, ctx.evZero[k], 0);

        bool isPred = (k < chunksPerCloud);
        const float* srcCloud = isPred ? pred : gt;
        int npb = isPred ? npbPred : npbGt;
        int ck = isPred ? k : (k - chunksPerCloud);
        int nPts = BPC * npb;

        const float* src = srcCloud + (long long)ck * BPC * npb * 3;
        float* dst = out + (long long)k * chunkFloats;

        int nThr = (nPts + 1) / 2;
        int blocks = (nThr + threads - 1) / threads;
        gridding_scatter2_kernel<<<blocks, threads>>>(
            src, dst, nPts, npb, R, Rf, invR, R3);
        cudaEventRecord(ctx.evScat[k], 0);
    }
    // Main stream's last op waited on evZero[NCHUNK-1]; side stream's last
    // memset precedes it -> side stream is rejoined at the final scatter.
}